// round 14
// baseline (speedup 1.0000x reference)
#include <cuda_runtime.h>
#include <cuda_fp16.h>
#include <cstdint>

// Block-sparse batched linear, single fused persistent kernel (sm_103-safe):
//   Y[i] = sum_{k: i_idx[k]==i} ( X[j_idx[k]] @ W[k] + b[k] )
// Round 13: X is converted fp32->fp16 ON THE FLY inside the GEMM pipeline
// (LDG f32 early -> cvt in regs -> STS at end of chunk), removing the
// serialized phase-1a prep (~25 us). Only W transpose+convert remains before
// the global barrier. GEMM core unchanged (it sits at the legacy-HMMA
// hardware floor): CTA 128x128, 4 warps (64x64 tiles), fp16
// mma.sync.m16n8k16 w/ f32 accum, 4-stage pipeline, 2 CTAs/SM, persistent.

namespace {

constexpr int NBLK   = 12;
constexpr int DDIM   = 256;
constexpr int BATCHN = 8192;
constexpr int NACT   = 48;

constexpr int BM = 128;
constexpr int BN = 128;
constexpr int BK = 32;
constexpr int NCH = 32;          // 4 active blocks * 8 k-chunks per tile
constexpr int NSTG = 4;
constexpr int THREADS = 128;
constexpr int GRIDP  = 296;      // 2 CTAs/SM; co-resident on 148/152-SM parts
constexpr int NT     = NBLK * (DDIM / BN) * (BATCHN / BM);   // 1536 tiles

constexpr uint32_t ROWB  = 80;            // 64B data + 16B pad per 32-elem row
constexpr uint32_t ASZ   = 128 * ROWB;    // 10240 B per operand tile
constexpr uint32_t OFF_A = 0;
constexpr uint32_t OFF_B = ASZ;
constexpr uint32_t STAGE_BYTES = 2 * ASZ;                  // 20480
constexpr uint32_t SM_BIAS     = NSTG * STAGE_BYTES;       // 81920
constexpr uint32_t SMEM_TOTAL  = SM_BIAS + 128 * 4;        // 82432

// ---- device scratch (static; no runtime allocation) ----
__device__ __half g_Wtf[(size_t)NACT * DDIM * DDIM];   // [blk][n][k]
__device__ unsigned int g_bar;   // monotonic ticket barrier (graph-replay safe)

// ---------------- helpers ----------------
__device__ __forceinline__ uint32_t smem_u32(const void* p) {
    uint32_t a;
    asm("{ .reg .u64 t; cvta.to.shared.u64 t, %1; cvt.u32.u64 %0, t; }"
        : "=r"(a) : "l"(p));
    return a;
}
__device__ __forceinline__ void cp16(uint32_t dst, const void* src) {
    asm volatile("cp.async.cg.shared.global [%0], [%1], 16;\n" :: "r"(dst), "l"(src));
}
__device__ __forceinline__ void cp_commit() { asm volatile("cp.async.commit_group;\n"); }
template <int N>
__device__ __forceinline__ void cp_wait() { asm volatile("cp.async.wait_group %0;\n" :: "n"(N)); }

__device__ __forceinline__ void sts64(uint32_t addr, uint2 v) {
    asm volatile("st.shared.v2.u32 [%0], {%1, %2};\n"
                 :: "r"(addr), "r"(v.x), "r"(v.y));
}
__device__ __forceinline__ void ldsm4(uint32_t r[4], uint32_t addr) {
    asm volatile("ldmatrix.sync.aligned.m8n8.x4.shared.b16 {%0,%1,%2,%3}, [%4];"
                 : "=r"(r[0]), "=r"(r[1]), "=r"(r[2]), "=r"(r[3]) : "r"(addr));
}
__device__ __forceinline__ void mma_f16(float d[4], const uint32_t a[4],
                                        uint32_t b0, uint32_t b1) {
    asm volatile(
        "mma.sync.aligned.m16n8k16.row.col.f32.f16.f16.f32 "
        "{%0,%1,%2,%3}, {%4,%5,%6,%7}, {%8,%9}, {%0,%1,%2,%3};\n"
        : "+f"(d[0]), "+f"(d[1]), "+f"(d[2]), "+f"(d[3])
        : "r"(a[0]), "r"(a[1]), "r"(a[2]), "r"(a[3]), "r"(b0), "r"(b1));
}
__device__ __forceinline__ uint2 cvt4(float4 v) {
    __half2 p0 = __floats2half2_rn(v.x, v.y);
    __half2 p1 = __floats2half2_rn(v.z, v.w);
    return make_uint2(*reinterpret_cast<uint32_t*>(&p0),
                      *reinterpret_cast<uint32_t*>(&p1));
}

struct Tile {
    int m0, n0, ib;
    int kact[4], jact[4];
};

__device__ __forceinline__ void decode_tile(int t, const int* i_idx,
                                            const int* j_idx, Tile& tl) {
    const int ibnh = t % 24;          // (ib, n-half) fastest -> L2 sharing
    tl.ib = ibnh >> 1;
    tl.n0 = (ibnh & 1) * BN;
    tl.m0 = (t / 24) * BM;
    int na = 0;
    #pragma unroll 1
    for (int k = 0; k < NACT; ++k) {
        if (__ldg(i_idx + k) == tl.ib) {
            if (na < 4) { tl.kact[na] = k; tl.jact[na] = __ldg(j_idx + k); }
            ++na;
        }
    }
}

// A source: raw X (f32). B source: preconverted transposed W (fp16).
__device__ __forceinline__ void chunk_srcs(const Tile& tl, int c,
                                           const float* X,
                                           const float*& A, const __half*& B) {
    const int a  = c >> 3;
    const int kk = (c & 7) * BK;
    A = X     + ((size_t)tl.jact[a] * BATCHN + tl.m0) * DDIM + kk;
    B = g_Wtf + ((size_t)tl.kact[a] * DDIM + tl.n0) * DDIM + kk;
}

// B tile cp.async: 512 slots of 16B, 4 per thread.
__device__ __forceinline__ void load_B(uint32_t stage_base, int tid, const __half* B) {
    #pragma unroll
    for (int t = 0; t < 4; ++t) {
        const int slot = tid + t * THREADS;       // 0..511
        const int row  = slot >> 2;               // 0..127
        const int c16  = slot & 3;
        cp16(stage_base + OFF_B + (uint32_t)row * ROWB + (uint32_t)c16 * 16,
             B + (size_t)row * DDIM + c16 * 8);
    }
}

// A chunk LDG (f32) -> fp16 regs: 1024 float4 slots, 8 per thread.
__device__ __forceinline__ void load_A_regs(const float* A, int tid, uint2 r[8]) {
    #pragma unroll
    for (int t = 0; t < 8; ++t) {
        const int slot = tid + t * THREADS;       // 0..1023
        const int row  = slot >> 3;               // 0..127 (8 float4 per row)
        const int c4   = (slot & 7) << 2;         // f32 col
        r[t] = cvt4(*reinterpret_cast<const float4*>(A + (size_t)row * DDIM + c4));
    }
}
__device__ __forceinline__ void store_A_regs(uint32_t stage_base, int tid,
                                             const uint2 r[8]) {
    #pragma unroll
    for (int t = 0; t < 8; ++t) {
        const int slot = tid + t * THREADS;
        const int row  = slot >> 3;
        const int c4   = (slot & 7) << 2;
        sts64(stage_base + OFF_A + (uint32_t)row * ROWB + (uint32_t)c4 * 2, r[t]);
    }
}

// ---------------- the single fused kernel ----------------
__global__ void __launch_bounds__(THREADS, 2)
bs_fused_kernel(const float* __restrict__ X,
                const float* __restrict__ W,
                const float* __restrict__ Bv,
                const int*   __restrict__ i_idx,
                const int*   __restrict__ j_idx,
                float*       __restrict__ Y)
{
    extern __shared__ __align__(128) char smem[];
    const uint32_t sb = smem_u32(smem);
    const int tid = threadIdx.x;

    // ============ phase 1: W -> transposed [n][k] fp16 (smem tiles) =======
    {
        float* ts = reinterpret_cast<float*>(smem);       // 32x33 f32 tile
        const int ty = tid >> 5, tx = tid & 31;           // ty 0..3
        #pragma unroll 1
        for (int s = blockIdx.x; s < NACT * 64; s += GRIDP) {
            const int blk = s >> 6, r = s & 63;
            const int k0 = (r >> 3) * 32, n0 = (r & 7) * 32;
            __syncthreads();   // protect previous subtile reads
            #pragma unroll
            for (int j = 0; j < 8; ++j) {
                const int y = ty + j * 4;
                ts[y * 33 + tx] =
                    W[((size_t)blk * DDIM + k0 + y) * DDIM + n0 + tx];
            }
            __syncthreads();
            #pragma unroll
            for (int j = 0; j < 8; ++j) {
                const int y = ty + j * 4;  // n-offset
                g_Wtf[((size_t)blk * DDIM + n0 + y) * DDIM + k0 + tx] =
                    __float2half_rn(ts[tx * 33 + y]);
            }
        }
    }

    // ================= global software barrier =================
    __threadfence();
    __syncthreads();
    if (tid == 0) {
        const unsigned ticket = atomicAdd(&g_bar, 1u);
        const unsigned target = (ticket / GRIDP + 1u) * GRIDP;
        unsigned v;
        do {
            asm volatile("ld.volatile.global.u32 %0, [%1];"
                         : "=r"(v) : "l"(&g_bar));
        } while (v < target);
    }
    __syncthreads();
    __threadfence();

    // ================= phase 2: persistent GEMM =================
    const int wid    = tid >> 5;
    const int lane   = tid & 31;
    const int g      = lane >> 2;
    const int tg     = lane & 3;
    const int warp_m = wid >> 1;     // 0..1  (64 rows)
    const int warp_n = wid & 1;      // 0..1  (64 cols)
    const int lrow   = lane & 15;
    const int lseg   = lane >> 4;

    int cur_t = blockIdx.x;
    if (cur_t >= NT) return;
    int nxt_t = cur_t + GRIDP;
    bool nxtv = nxt_t < NT;

    Tile cur, nxt;
    decode_tile(cur_t, i_idx, j_idx, cur);
    if (nxtv) decode_tile(nxt_t, i_idx, j_idx, nxt);

    // prologue: chunks 0..2 -> stages 0..2 (A synchronous, B async)
    #pragma unroll
    for (int c = 0; c < NSTG - 1; ++c) {
        const float* A; const __half* B;
        chunk_srcs(cur, c, X, A, B);
        uint2 ar[8];
        load_A_regs(A, tid, ar);
        store_A_regs(sb + (uint32_t)c * STAGE_BYTES, tid, ar);
        load_B(sb + (uint32_t)c * STAGE_BYTES, tid, B);
        cp_commit();
    }
    uint32_t gs = 0;   // global chunk counter; stage = gs & 3

    for (;;) {
        float acc[4][8][4];
        #pragma unroll
        for (int mt = 0; mt < 4; ++mt)
            #pragma unroll
            for (int nt = 0; nt < 8; ++nt)
                #pragma unroll
                for (int q = 0; q < 4; ++q)
                    acc[mt][nt][q] = 0.0f;

        for (int c = 0; c < NCH; ++c) {
            cp_wait<NSTG - 2>();      // chunk gs's B resident (A by program order)
            __syncthreads();          // protects stage (gs+3)&3 reuse

            // ---- prefetch chunk c+3 (this tile or next): A LDG early,
            // ---- B cp.async now, A STS after the MMA burst.
            const int pc = c + NSTG - 1;
            const bool pv = (pc < NCH) || nxtv;
            uint2 ar[8];
            if (pv) {
                const float* A; const __half* B;
                if (pc < NCH) chunk_srcs(cur, pc, X, A, B);
                else          chunk_srcs(nxt, pc - NCH, X, A, B);
                load_A_regs(A, tid, ar);    // LDG latency hidden by MMA burst
                load_B(sb + (uint32_t)((gs + 3) & 3) * STAGE_BYTES, tid, B);
            }
            cp_commit();              // keeps group accounting aligned

            const uint32_t st = sb + (uint32_t)(gs & 3) * STAGE_BYTES;
            const uint32_t aB = st + OFF_A, bB = st + OFF_B;

            #pragma unroll
            for (int h = 0; h < 2; ++h) {
                const uint32_t fcol = (uint32_t)(h * 32 + lseg * 16);
                const uint32_t bo = (uint32_t)(warp_n * 64 + lrow) * ROWB + fcol;
                uint32_t b[4][4];
                ldsm4(b[0], bB + bo);
                ldsm4(b[1], bB + bo + 16 * ROWB);
                ldsm4(b[2], bB + bo + 32 * ROWB);
                ldsm4(b[3], bB + bo + 48 * ROWB);

                #pragma unroll
                for (int mt = 0; mt < 4; ++mt) {
                    const uint32_t ao =
                        (uint32_t)(warp_m * 64 + mt * 16 + lrow) * ROWB + fcol;
                    uint32_t a[4];
                    ldsm4(a, aB + ao);
                    #pragma unroll
                    for (int t = 0; t < 4; ++t) {
                        mma_f16(acc[mt][t * 2 + 0], a, b[t][0], b[t][2]);
                        mma_f16(acc[mt][t * 2 + 1], a, b[t][1], b[t][3]);
                    }
                }
            }

            if (pv)   // A data for chunk gs+3; readers gated by 3 barriers
                store_A_regs(sb + (uint32_t)((gs + 3) & 3) * STAGE_BYTES, tid, ar);
            ++gs;
        }

        // ---- epilogue for cur (next tile's prefetches in flight)
        __syncthreads();
        if (tid < BN) {
            const int col = cur.n0 + tid;
            float bs = __ldg(Bv + (size_t)cur.kact[0] * DDIM + col)
                     + __ldg(Bv + (size_t)cur.kact[1] * DDIM + col)
                     + __ldg(Bv + (size_t)cur.kact[2] * DDIM + col)
                     + __ldg(Bv + (size_t)cur.kact[3] * DDIM + col);
            reinterpret_cast<float*>(smem + SM_BIAS)[tid] = bs;
        }
        __syncthreads();
        const float* biasp = reinterpret_cast<const float*>(smem + SM_BIAS);

        #pragma unroll
        for (int mt = 0; mt < 4; ++mt) {
            const int row = cur.m0 + warp_m * 64 + mt * 16 + g;
            #pragma unroll
            for (int nt = 0; nt < 8; ++nt) {
                const int lc  = warp_n * 64 + nt * 8 + tg * 2;
                const float b0 = biasp[lc], b1 = biasp[lc + 1];
                const size_t o0 =
                    ((size_t)cur.ib * BATCHN + row) * DDIM + cur.n0 + lc;
                const size_t o1 = o0 + (size_t)8 * DDIM;
                *reinterpret_cast<float2*>(Y + o0) =
                    make_float2(acc[mt][nt][0] + b0, acc[mt][nt][1] + b1);
                *reinterpret_cast<float2*>(Y + o1) =
                    make_float2(acc[mt][nt][2] + b0, acc[mt][nt][3] + b1);
            }
        }

        if (!nxtv) break;
        cur = nxt;
        nxt_t += GRIDP;
        nxtv = nxt_t < NT;
        if (nxtv) decode_tile(nxt_t, i_idx, j_idx, nxt);
        __syncthreads();   // bias smem reuse guard
    }
}

} // namespace

extern "C" void kernel_launch(void* const* d_in, const int* in_sizes, int n_in,
                              void* d_out, int out_size) {
    const float* X     = (const float*)d_in[0];
    const float* W     = (const float*)d_in[1];
    const float* b     = (const float*)d_in[2];
    const int*   i_idx = (const int*)d_in[3];
    const int*   j_idx = (const int*)d_in[4];
    float*       Y     = (float*)d_out;

    cudaFuncSetAttribute(bs_fused_kernel,
                         cudaFuncAttributeMaxDynamicSharedMemorySize, SMEM_TOTAL);

    bs_fused_kernel<<<GRIDP, THREADS, SMEM_TOTAL>>>(X, W, b, i_idx, j_idx, Y);
}

// round 15
// speedup vs baseline: 1.0804x; 1.0804x over previous
#include <cuda_runtime.h>
#include <cuda_fp16.h>
#include <cstdint>

// Block-sparse batched linear, single fused persistent kernel (sm_103-safe):
//   Y[i] = sum_{k: i_idx[k]==i} ( X[j_idx[k]] @ W[k] + b[k] )
// Round 15: A operand stays fp32 -- cp.async'd directly from X into smem and
// converted to fp16 PER FRAGMENT (4x LDS.64 + 4x cvt.rn.f16x2) at the MMA
// boundary. This deletes the serialized X->fp16 prep pass (~25 us) without
// the register-staging cost that sank round 13. W is still pre-transposed/
// converted (tiny, ~3 us) before a ticket barrier. GEMM core otherwise
// unchanged: CTA 128x128, 4 warps (64x64 tiles), fp16 mma.sync.m16n8k16
// w/ f32 accum, 4-stage pipeline, persistent 296 CTAs (2/SM).

namespace {

constexpr int NBLK   = 12;
constexpr int DDIM   = 256;
constexpr int BATCHN = 8192;
constexpr int NACT   = 48;

constexpr int BM = 128;
constexpr int BN = 128;
constexpr int BK = 32;
constexpr int NCH = 32;          // 4 active blocks * 8 k-chunks per tile
constexpr int NSTG = 4;
constexpr int THREADS = 128;
constexpr int GRIDP  = 296;      // 2 CTAs/SM; co-resident on 148/152-SM parts
constexpr int NT     = NBLK * (DDIM / BN) * (BATCHN / BM);   // 1536 tiles

constexpr uint32_t ROWBA = 144;           // A: 32 f32 = 128B data + 16B pad
constexpr uint32_t ROWBB = 80;            // B: 32 f16 = 64B data + 16B pad
constexpr uint32_t A_SZ  = 128 * ROWBA;   // 18432 B (f32 tile)
constexpr uint32_t B_SZ  = 128 * ROWBB;   // 10240 B (f16 tile)
constexpr uint32_t OFF_A = 0;
constexpr uint32_t OFF_B = A_SZ;
constexpr uint32_t STAGE_BYTES = A_SZ + B_SZ;              // 28672
constexpr uint32_t SM_BIAS     = NSTG * STAGE_BYTES;       // 114688
constexpr uint32_t SMEM_TOTAL  = SM_BIAS + 128 * 4;        // 115200 (2 CTA/SM)

// ---- device scratch (static; no runtime allocation) ----
__device__ __half g_Wtf[(size_t)NACT * DDIM * DDIM];   // [blk][n][k]
__device__ unsigned int g_bar;   // monotonic ticket barrier (graph-replay safe)

// ---------------- helpers ----------------
__device__ __forceinline__ uint32_t smem_u32(const void* p) {
    uint32_t a;
    asm("{ .reg .u64 t; cvta.to.shared.u64 t, %1; cvt.u32.u64 %0, t; }"
        : "=r"(a) : "l"(p));
    return a;
}
__device__ __forceinline__ void cp16(uint32_t dst, const void* src) {
    asm volatile("cp.async.cg.shared.global [%0], [%1], 16;\n" :: "r"(dst), "l"(src));
}
__device__ __forceinline__ void cp_commit() { asm volatile("cp.async.commit_group;\n"); }
template <int N>
__device__ __forceinline__ void cp_wait() { asm volatile("cp.async.wait_group %0;\n" :: "n"(N)); }

__device__ __forceinline__ void ldsm4(uint32_t r[4], uint32_t addr) {
    asm volatile("ldmatrix.sync.aligned.m8n8.x4.shared.b16 {%0,%1,%2,%3}, [%4];"
                 : "=r"(r[0]), "=r"(r[1]), "=r"(r[2]), "=r"(r[3]) : "r"(addr));
}
__device__ __forceinline__ void mma_f16(float d[4], const uint32_t a[4],
                                        uint32_t b0, uint32_t b1) {
    asm volatile(
        "mma.sync.aligned.m16n8k16.row.col.f32.f16.f16.f32 "
        "{%0,%1,%2,%3}, {%4,%5,%6,%7}, {%8,%9}, {%0,%1,%2,%3};\n"
        : "+f"(d[0]), "+f"(d[1]), "+f"(d[2]), "+f"(d[3])
        : "r"(a[0]), "r"(a[1]), "r"(a[2]), "r"(a[3]), "r"(b0), "r"(b1));
}

// Load one f32 pair from smem and pack to fp16x2 (same rounding as prep did).
__device__ __forceinline__ uint32_t lds_f2h2(uint32_t addr) {
    float x, y;
    asm volatile("ld.shared.v2.f32 {%0, %1}, [%2];" : "=f"(x), "=f"(y) : "r"(addr));
    __half2 h = __floats2half2_rn(x, y);
    return *reinterpret_cast<uint32_t*>(&h);
}

struct Tile {
    int m0, n0, ib;
    int kact[4], jact[4];
};

__device__ __forceinline__ void decode_tile(int t, const int* i_idx,
                                            const int* j_idx, Tile& tl) {
    const int ibnh = t % 24;          // (ib, n-half) fastest -> L2 sharing
    tl.ib = ibnh >> 1;
    tl.n0 = (ibnh & 1) * BN;
    tl.m0 = (t / 24) * BM;
    int na = 0;
    #pragma unroll 1
    for (int k = 0; k < NACT; ++k) {
        if (__ldg(i_idx + k) == tl.ib) {
            if (na < 4) { tl.kact[na] = k; tl.jact[na] = __ldg(j_idx + k); }
            ++na;
        }
    }
}

// A source: raw X (f32). B source: preconverted transposed W (fp16).
__device__ __forceinline__ void chunk_srcs(const Tile& tl, int c,
                                           const float* X,
                                           const float*& A, const __half*& B) {
    const int a  = c >> 3;
    const int kk = (c & 7) * BK;
    A = X     + ((size_t)tl.jact[a] * BATCHN + tl.m0) * DDIM + kk;
    B = g_Wtf + ((size_t)tl.kact[a] * DDIM + tl.n0) * DDIM + kk;
}

// Chunk load: A f32 (1024 float4 slots, 8/thread) + B f16 (512 16B, 4/thread).
__device__ __forceinline__ void load_chunk(
    uint32_t stage_base, int tid, const float* A, const __half* B)
{
    #pragma unroll
    for (int t = 0; t < 8; ++t) {
        const int slot = tid + t * THREADS;       // 0..1023
        const int row  = slot >> 3;               // 0..127 (8 float4 per row)
        const int c4   = slot & 7;                // float4 index in row
        cp16(stage_base + OFF_A + (uint32_t)row * ROWBA + (uint32_t)c4 * 16,
             A + (size_t)row * DDIM + c4 * 4);
    }
    #pragma unroll
    for (int t = 0; t < 4; ++t) {
        const int slot = tid + t * THREADS;       // 0..511
        const int row  = slot >> 2;
        const int c16  = slot & 3;
        cp16(stage_base + OFF_B + (uint32_t)row * ROWBB + (uint32_t)c16 * 16,
             B + (size_t)row * DDIM + c16 * 8);
    }
}

// ---------------- the single fused kernel ----------------
__global__ void __launch_bounds__(THREADS, 2)
bs_fused_kernel(const float* __restrict__ X,
                const float* __restrict__ W,
                const float* __restrict__ Bv,
                const int*   __restrict__ i_idx,
                const int*   __restrict__ j_idx,
                float*       __restrict__ Y)
{
    extern __shared__ __align__(128) char smem[];
    const uint32_t sb = smem_u32(smem);
    const int tid = threadIdx.x;

    // ============ phase 1: W -> transposed [n][k] fp16 (smem tiles) =======
    {
        float* ts = reinterpret_cast<float*>(smem);       // 32x33 f32 tile
        const int ty = tid >> 5, tx = tid & 31;           // ty 0..3
        #pragma unroll 1
        for (int s = blockIdx.x; s < NACT * 64; s += GRIDP) {
            const int blk = s >> 6, r = s & 63;
            const int k0 = (r >> 3) * 32, n0 = (r & 7) * 32;
            __syncthreads();   // protect previous subtile reads
            #pragma unroll
            for (int j = 0; j < 8; ++j) {
                const int y = ty + j * 4;
                ts[y * 33 + tx] =
                    W[((size_t)blk * DDIM + k0 + y) * DDIM + n0 + tx];
            }
            __syncthreads();
            #pragma unroll
            for (int j = 0; j < 8; ++j) {
                const int y = ty + j * 4;  // n-offset
                g_Wtf[((size_t)blk * DDIM + n0 + y) * DDIM + k0 + tx] =
                    __float2half_rn(ts[tx * 33 + y]);
            }
        }
    }

    // ================= global software barrier =================
    __threadfence();
    __syncthreads();
    if (tid == 0) {
        const unsigned ticket = atomicAdd(&g_bar, 1u);
        const unsigned target = (ticket / GRIDP + 1u) * GRIDP;
        unsigned v;
        do {
            asm volatile("ld.volatile.global.u32 %0, [%1];"
                         : "=r"(v) : "l"(&g_bar));
        } while (v < target);
    }
    __syncthreads();
    __threadfence();

    // ================= phase 2: persistent GEMM =================
    const int wid    = tid >> 5;
    const int lane   = tid & 31;
    const int g      = lane >> 2;
    const int tg     = lane & 3;
    const int warp_m = wid >> 1;     // 0..1  (64 rows)
    const int warp_n = wid & 1;      // 0..1  (64 cols)
    const int lrow   = lane & 15;
    const int lseg   = lane >> 4;

    int cur_t = blockIdx.x;
    if (cur_t >= NT) return;
    int nxt_t = cur_t + GRIDP;
    bool nxtv = nxt_t < NT;

    Tile cur, nxt;
    decode_tile(cur_t, i_idx, j_idx, cur);
    if (nxtv) decode_tile(nxt_t, i_idx, j_idx, nxt);

    #pragma unroll
    for (int c = 0; c < NSTG - 1; ++c) {
        const float* A; const __half* B;
        chunk_srcs(cur, c, X, A, B);
        load_chunk(sb + (uint32_t)c * STAGE_BYTES, tid, A, B);
        cp_commit();
    }
    uint32_t gs = 0;   // global chunk counter; stage = gs & 3

    for (;;) {
        float acc[4][8][4];
        #pragma unroll
        for (int mt = 0; mt < 4; ++mt)
            #pragma unroll
            for (int nt = 0; nt < 8; ++nt)
                #pragma unroll
                for (int q = 0; q < 4; ++q)
                    acc[mt][nt][q] = 0.0f;

        for (int c = 0; c < NCH; ++c) {
            cp_wait<NSTG - 2>();      // chunk gs resident
            __syncthreads();          // protects stage (gs+3)&3 reuse

            const int pc = c + NSTG - 1;
            if (pc < NCH) {
                const float* A; const __half* B;
                chunk_srcs(cur, pc, X, A, B);
                load_chunk(sb + (uint32_t)((gs + 3) & 3) * STAGE_BYTES, tid, A, B);
            } else if (nxtv) {        // prefetch next tile's chunks 0..2
                const float* A; const __half* B;
                chunk_srcs(nxt, pc - NCH, X, A, B);
                load_chunk(sb + (uint32_t)((gs + 3) & 3) * STAGE_BYTES, tid, A, B);
            }
            cp_commit();              // keeps group accounting aligned

            const uint32_t st = sb + (uint32_t)(gs & 3) * STAGE_BYTES;
            const uint32_t aB = st + OFF_A, bB = st + OFF_B;

            #pragma unroll
            for (int h = 0; h < 2; ++h) {
                // B fragments via ldmatrix (fp16 tile, unchanged)
                const uint32_t fcol = (uint32_t)(h * 32 + lseg * 16);
                const uint32_t bo = (uint32_t)(warp_n * 64 + lrow) * ROWBB + fcol;
                uint32_t b[4][4];
                ldsm4(b[0], bB + bo);
                ldsm4(b[1], bB + bo + 16 * ROWBB);
                ldsm4(b[2], bB + bo + 32 * ROWBB);
                ldsm4(b[3], bB + bo + 48 * ROWBB);

                // A fragments: f32 smem -> per-thread LDS.64 + cvt to fp16x2
                const uint32_t kcb = (uint32_t)(h * 16 + tg * 2) * 4;  // byte col
                #pragma unroll
                for (int mt = 0; mt < 4; ++mt) {
                    const uint32_t r0 =
                        (uint32_t)(warp_m * 64 + mt * 16 + g) * ROWBA;
                    uint32_t a[4];
                    a[0] = lds_f2h2(aB + r0 + kcb);
                    a[1] = lds_f2h2(aB + r0 + 8 * ROWBA + kcb);
                    a[2] = lds_f2h2(aB + r0 + kcb + 32);            // k+8
                    a[3] = lds_f2h2(aB + r0 + 8 * ROWBA + kcb + 32);
                    #pragma unroll
                    for (int t = 0; t < 4; ++t) {
                        mma_f16(acc[mt][t * 2 + 0], a, b[t][0], b[t][2]);
                        mma_f16(acc[mt][t * 2 + 1], a, b[t][1], b[t][3]);
                    }
                }
            }
            ++gs;
        }

        // ---- epilogue for cur (next tile's prefetches in flight)
        __syncthreads();
        if (tid < BN) {
            const int col = cur.n0 + tid;
            float bs = __ldg(Bv + (size_t)cur.kact[0] * DDIM + col)
                     + __ldg(Bv + (size_t)cur.kact[1] * DDIM + col)
                     + __ldg(Bv + (size_t)cur.kact[2] * DDIM + col)
                     + __ldg(Bv + (size_t)cur.kact[3] * DDIM + col);
            reinterpret_cast<float*>(smem + SM_BIAS)[tid] = bs;
        }
        __syncthreads();
        const float* biasp = reinterpret_cast<const float*>(smem + SM_BIAS);

        #pragma unroll
        for (int mt = 0; mt < 4; ++mt) {
            const int row = cur.m0 + warp_m * 64 + mt * 16 + g;
            #pragma unroll
            for (int nt = 0; nt < 8; ++nt) {
                const int lc  = warp_n * 64 + nt * 8 + tg * 2;
                const float b0 = biasp[lc], b1 = biasp[lc + 1];
                const size_t o0 =
                    ((size_t)cur.ib * BATCHN + row) * DDIM + cur.n0 + lc;
                const size_t o1 = o0 + (size_t)8 * DDIM;
                *reinterpret_cast<float2*>(Y + o0) =
                    make_float2(acc[mt][nt][0] + b0, acc[mt][nt][1] + b1);
                *reinterpret_cast<float2*>(Y + o1) =
                    make_float2(acc[mt][nt][2] + b0, acc[mt][nt][3] + b1);
            }
        }

        if (!nxtv) break;
        cur = nxt;
        nxt_t += GRIDP;
        nxtv = nxt_t < NT;
        if (nxtv) decode_tile(nxt_t, i_idx, j_idx, nxt);
        __syncthreads();   // bias smem reuse guard
    }
}

} // namespace

extern "C" void kernel_launch(void* const* d_in, const int* in_sizes, int n_in,
                              void* d_out, int out_size) {
    const float* X     = (const float*)d_in[0];
    const float* W     = (const float*)d_in[1];
    const float* b     = (const float*)d_in[2];
    const int*   i_idx = (const int*)d_in[3];
    const int*   j_idx = (const int*)d_in[4];
    float*       Y     = (float*)d_out;

    cudaFuncSetAttribute(bs_fused_kernel,
                         cudaFuncAttributeMaxDynamicSharedMemorySize, SMEM_TOTAL);

    bs_fused_kernel<<<GRIDP, THREADS, SMEM_TOTAL>>>(X, W, b, i_idx, j_idx, Y);
}